// round 15
// baseline (speedup 1.0000x reference)
#include <cuda_runtime.h>
#include <cstdint>

// Twist2Mat (Rodrigues): twist [B,R,3] f32 -> rot [B,R,3,3] f32
// N = B*R = 8,388,608. Memory-bound: 384 MB streaming (96 read / 288 write).
//
// History: R1 166us -> R2 66.3 (smem staging) -> R3 63.9 (warp tiles + ldcs)
// -> R9/R14 paired 2304B evict_first TMA stores = BEST (63.55-63.58 harness,
// 58.56 profile, DRAM 74.2%). R4/5/7/10/11/13 neutral, R12 persistent
// regressed (16 warps/SM starved reads). Plateau ~5.85 TB/s = HBM 1R:3W
// ceiling.
// R15: 256 elems/warp (TILES=8) at TPB=128 -> half the warp-lifetimes, each
// exposed DRAM load amortized over 2x work; 28 warps/SM stays in the proven
// sufficient band. Stores: 4x 2304B evict_first TMA, 2 rotating buffers
// gated by wait_group.read 1.

#define TPB 128
#define WARPS (TPB / 32)
#define TILES 8            // 32-element tiles per warp => 256 elems/warp

__device__ __forceinline__ void rodrigues9(float x, float y, float z, float* __restrict__ r)
{
    float n2    = fmaf(x, x, fmaf(y, y, z * z));
    float theta = fmaxf(sqrtf(n2), 1e-5f);
    float inv   = __fdividef(1.0f, theta);
    float a0 = x * inv, a1 = y * inv, a2 = z * inv;

    float s, c;
    __sincosf(theta, &s, &c);
    float k = 1.0f - c;

    // R = c*I + s*[a]_x + k*(a a^T)
    float ka0 = k * a0, ka1 = k * a1;
    float sa0 = s * a0, sa1 = s * a1, sa2 = s * a2;

    r[0] = fmaf(ka0, a0, c);
    r[1] = fmaf(ka0, a1, -sa2);
    r[2] = fmaf(ka0, a2,  sa1);
    r[3] = fmaf(ka0, a1,  sa2);
    r[4] = fmaf(ka1, a1, c);
    r[5] = fmaf(ka1, a2, -sa0);
    r[6] = fmaf(ka0, a2, -sa1);
    r[7] = fmaf(ka1, a2,  sa0);
    r[8] = fmaf(k * a2, a2, c);
}

__global__ __launch_bounds__(TPB)
void twist2mat_r15_kernel(const float4* __restrict__ in4,
                          float4* __restrict__ out4,
                          int n_elems)
{
    __shared__ float s_in [WARPS][TILES * 96];                 // 3072 B / warp
    __shared__ __align__(16) float s_out[WARPS][2][576];       // 2 x 2304 B / warp
    // static smem: 4*(3072+4608) = 30720 B < 48 KB

    const int lane = threadIdx.x & 31;
    const int wrp  = threadIdx.x >> 5;
    const long long wstart = ((long long)blockIdx.x * WARPS + wrp) * (32 * TILES);
    if (wstart >= n_elems) return;

    const float4* gin  = in4  + wstart / 4 * 3;   // wstart*3/4
    float4*       gout = out4 + wstart / 4 * 9;   // wstart*9/4

    const bool warp_full = (wstart + 32 * TILES <= n_elems);

    // ---- batched coalesced load: 192 float4 per warp (6 per lane) ----
    if (warp_full) {
        float4* s = (float4*)s_in[wrp];
#pragma unroll
        for (int j = 0; j < 6; j++)
            s[lane + 32 * j] = __ldcs(gin + lane + 32 * j);
    } else {
        const float* gf = (const float*)gin;
        int vf = (int)(n_elems - wstart) * 3;
        for (int i = lane; i < TILES * 96; i += 32)
            s_in[wrp][i] = (i < vf) ? gf[i] : 1.0f;   // pad, never stored
    }
    __syncwarp();

    if (warp_full) {
        // evict_first policy for the streaming write lines
        uint64_t pol;
        asm volatile("createpolicy.fractional.L2::evict_first.b64 %0, 1.0;" : "=l"(pol));

#pragma unroll
        for (int p = 0; p < TILES / 2; p++) {
            // Buffer (p&1) is reusable once the bulk store committed at pair
            // p-2 has finished READING it; groups retire in order, so
            // "at most 1 pending" suffices.
            if (p >= 2) {
                if (lane == 0)
                    asm volatile("cp.async.bulk.wait_group.read 1;" ::: "memory");
                __syncwarp();
            }

            // ---- compute two tiles into one contiguous 2304B buffer ----
            float* sop = s_out[wrp][p & 1];
#pragma unroll
            for (int sub = 0; sub < 2; sub++) {
                const int t = 2 * p + sub;
                const float* si = s_in[wrp] + t * 96;
                float x = si[3 * lane + 0];
                float y = si[3 * lane + 1];
                float z = si[3 * lane + 2];
                float r[9];
                rodrigues9(x, y, z, r);
                float* so = sop + sub * 288;
#pragma unroll
                for (int i = 0; i < 9; i++)
                    so[9 * lane + i] = r[i];          // stride-9 STS: conflict-free
            }
            __syncwarp();

            // ---- one TMA bulk store per pair: 2304 B, evict_first hint ----
            if (lane == 0) {
                asm volatile("fence.proxy.async.shared::cta;" ::: "memory");
                uint32_t src = (uint32_t)__cvta_generic_to_shared(sop);
                void* dst = (void*)(gout + p * 144);
                asm volatile(
                    "cp.async.bulk.global.shared::cta.bulk_group.L2::cache_hint "
                    "[%0], [%1], %2, %3;"
                    :: "l"(dst), "r"(src), "n"(2304), "l"(pol) : "memory");
                asm volatile("cp.async.bulk.commit_group;" ::: "memory");
            }
        }
        // Exit drain: smem-read completion only (safe for CTA retire).
        if (lane == 0)
            asm volatile("cp.async.bulk.wait_group.read 0;" ::: "memory");
    } else {
        // ---- scalar-safe tail path (not hit for this shape) ----
        for (int t = 0; t < TILES; t++) {
            const long long tbase = wstart + 32LL * t;
            if (tbase >= n_elems) break;
            const float* si = s_in[wrp] + t * 96;
            float r[9];
            rodrigues9(si[3 * lane], si[3 * lane + 1], si[3 * lane + 2], r);
            float* so = s_out[wrp][0];
#pragma unroll
            for (int i = 0; i < 9; i++)
                so[9 * lane + i] = r[i];
            __syncwarp();
            float* gf = (float*)(gout + t * 72);
            long long ve = n_elems - tbase;
            int vf = (int)((ve < 32 ? ve : 32) * 9);
            for (int i = lane; i < vf; i += 32)
                gf[i] = so[i];
            __syncwarp();
        }
    }
}

extern "C" void kernel_launch(void* const* d_in, const int* in_sizes, int n_in,
                              void* d_out, int out_size)
{
    const float* twist = (const float*)d_in[0];
    float* out = (float*)d_out;

    int n_elems = in_sizes[0] / 3;                       // 8,388,608
    long long per_block = (long long)WARPS * 32 * TILES; // 1024
    int blocks = (int)((n_elems + per_block - 1) / per_block);

    twist2mat_r15_kernel<<<blocks, TPB>>>((const float4*)twist, (float4*)out, n_elems);
}

// round 16
// speedup vs baseline: 1.0076x; 1.0076x over previous
#include <cuda_runtime.h>
#include <cstdint>

// Twist2Mat (Rodrigues): twist [B,R,3] f32 -> rot [B,R,3,3] f32
// N = B*R = 8,388,608. Memory-bound: 384 MB streaming (96 read / 288 write).
//
// FINAL KERNEL (= R14). Session summary:
//   R1  166.0us  per-thread strided stores (9x L1 wavefront amplification)
//   R2   66.3us  block smem staging, fully coalesced float4 I/O
//   R3   63.9us  warp-private tiles, __ldcs/__stcs
//   R9/R14 63.55-63.58us  paired 2304B evict_first TMA bulk stores
//                (best profile 58.56us, DRAM 74.2%, 5.88 TB/s)
//   Neutral: read-MLP batching, register prefetch, TMA bulk loads, 4608B
//   stores, drain semantics, 2x per-warp work. Regressed: persistence.
// Conclusion: pinned at ~5.85 TB/s aggregate = empirical HBM ceiling for a
// 1R:3W interleaved stream; every remaining per-op overhead trimmed.

#ifndef TPB
#define TPB 256
#endif
#define WARPS (TPB / 32)
#define TILES 4            // 32-element tiles per warp => 128 elems/warp

__device__ __forceinline__ void rodrigues9(float x, float y, float z, float* __restrict__ r)
{
    float n2    = fmaf(x, x, fmaf(y, y, z * z));
    float theta = fmaxf(sqrtf(n2), 1e-5f);
    float inv   = __fdividef(1.0f, theta);
    float a0 = x * inv, a1 = y * inv, a2 = z * inv;

    float s, c;
    __sincosf(theta, &s, &c);
    float k = 1.0f - c;

    // R = c*I + s*[a]_x + k*(a a^T)
    float ka0 = k * a0, ka1 = k * a1;
    float sa0 = s * a0, sa1 = s * a1, sa2 = s * a2;

    r[0] = fmaf(ka0, a0, c);
    r[1] = fmaf(ka0, a1, -sa2);
    r[2] = fmaf(ka0, a2,  sa1);
    r[3] = fmaf(ka0, a1,  sa2);
    r[4] = fmaf(ka1, a1, c);
    r[5] = fmaf(ka1, a2, -sa0);
    r[6] = fmaf(ka0, a2, -sa1);
    r[7] = fmaf(ka1, a2,  sa0);
    r[8] = fmaf(k * a2, a2, c);
}

__global__ __launch_bounds__(TPB)
void twist2mat_kernel(const float4* __restrict__ in4,
                      float4* __restrict__ out4,
                      int n_elems)
{
    __shared__ float s_in [WARPS][TILES * 96];                 // 1536 B / warp
    __shared__ __align__(16) float s_out[WARPS][2][576];       // 2 x 2304 B / warp

    const int lane = threadIdx.x & 31;
    const int wrp  = threadIdx.x >> 5;
    const long long wstart = ((long long)blockIdx.x * WARPS + wrp) * (32 * TILES);
    if (wstart >= n_elems) return;

    const float4* gin  = in4  + wstart / 4 * 3;   // wstart*3/4
    float4*       gout = out4 + wstart / 4 * 9;   // wstart*9/4

    const bool warp_full = (wstart + 32 * TILES <= n_elems);

    // ---- batched coalesced load: 96 float4 per warp (3 per lane) ----
    if (warp_full) {
        float4* s = (float4*)s_in[wrp];
#pragma unroll
        for (int j = 0; j < 3; j++)
            s[lane + 32 * j] = __ldcs(gin + lane + 32 * j);
    } else {
        const float* gf = (const float*)gin;
        int vf = (int)(n_elems - wstart) * 3;
        for (int i = lane; i < TILES * 96; i += 32)
            s_in[wrp][i] = (i < vf) ? gf[i] : 1.0f;   // pad, never stored
    }
    __syncwarp();

    if (warp_full) {
        // evict_first policy for the streaming write lines
        uint64_t pol;
        asm volatile("createpolicy.fractional.L2::evict_first.b64 %0, 1.0;" : "=l"(pol));

#pragma unroll
        for (int p = 0; p < TILES / 2; p++) {
            // ---- compute two tiles into one contiguous 2304B buffer ----
            float* sop = s_out[wrp][p];
#pragma unroll
            for (int sub = 0; sub < 2; sub++) {
                const int t = 2 * p + sub;
                const float* si = s_in[wrp] + t * 96;
                float x = si[3 * lane + 0];
                float y = si[3 * lane + 1];
                float z = si[3 * lane + 2];
                float r[9];
                rodrigues9(x, y, z, r);
                float* so = sop + sub * 288;
#pragma unroll
                for (int i = 0; i < 9; i++)
                    so[9 * lane + i] = r[i];          // stride-9 STS: conflict-free
            }
            __syncwarp();

            // ---- one TMA bulk store per pair: 2304 B, evict_first hint ----
            if (lane == 0) {
                asm volatile("fence.proxy.async.shared::cta;" ::: "memory");
                uint32_t src = (uint32_t)__cvta_generic_to_shared(sop);
                void* dst = (void*)(gout + p * 144);
                asm volatile(
                    "cp.async.bulk.global.shared::cta.bulk_group.L2::cache_hint "
                    "[%0], [%1], %2, %3;"
                    :: "l"(dst), "r"(src), "n"(2304), "l"(pol) : "memory");
                asm volatile("cp.async.bulk.commit_group;" ::: "memory");
            }
            // no mid-loop wait: each buffer is written exactly once
        }
        // Exit drain: smem-read completion only (safe for CTA retire);
        // do not wait for global write visibility.
        if (lane == 0)
            asm volatile("cp.async.bulk.wait_group.read 0;" ::: "memory");
    } else {
        // ---- scalar-safe tail path (not hit for this shape) ----
        for (int t = 0; t < TILES; t++) {
            const long long tbase = wstart + 32LL * t;
            if (tbase >= n_elems) break;
            const float* si = s_in[wrp] + t * 96;
            float r[9];
            rodrigues9(si[3 * lane], si[3 * lane + 1], si[3 * lane + 2], r);
            float* so = s_out[wrp][0];
#pragma unroll
            for (int i = 0; i < 9; i++)
                so[9 * lane + i] = r[i];
            __syncwarp();
            float* gf = (float*)(gout + t * 72);
            long long ve = n_elems - tbase;
            int vf = (int)((ve < 32 ? ve : 32) * 9);
            for (int i = lane; i < vf; i += 32)
                gf[i] = so[i];
            __syncwarp();
        }
    }
}

extern "C" void kernel_launch(void* const* d_in, const int* in_sizes, int n_in,
                              void* d_out, int out_size)
{
    const float* twist = (const float*)d_in[0];
    float* out = (float*)d_out;

    int n_elems = in_sizes[0] / 3;                       // 8,388,608
    long long per_block = (long long)WARPS * 32 * TILES; // 1024
    int blocks = (int)((n_elems + per_block - 1) / per_block);

    twist2mat_kernel<<<blocks, TPB>>>((const float4*)twist, (float4*)out, n_elems);
}

// round 17
// speedup vs baseline: 1.0091x; 1.0015x over previous
#include <cuda_runtime.h>
#include <cstdint>

// Twist2Mat (Rodrigues): twist [B,R,3] f32 -> rot [B,R,3,3] f32
// N = B*R = 8,388,608. Memory-bound: 384 MB streaming (96 read / 288 write).
//
// FINAL FAMILY (R14/R16 confirmed best: 63.52us harness / 58.43us profile,
// DRAM 74.1%, 5.88 TB/s). Session: R1 166us (strided stores, 9x L1 wf
// amplification) -> R2 smem staging 66.3 -> R3 warp tiles 63.9 -> R9/R14
// paired 2304B evict_first TMA stores 63.5. Neutral: read-MLP, prefetch,
// TMA loads, store granularity, drain semantics, 2x warp work. Regressed:
// persistence. Plateau = HBM 1R:3W interleaved-stream ceiling.
// R17: + L2::256B prefetch hint on the read stream (free hint bit; reads
// run ahead of demand, smoothing read/write interleave at the DRAM sched).

#ifndef TPB
#define TPB 256
#endif
#define WARPS (TPB / 32)
#define TILES 4            // 32-element tiles per warp => 128 elems/warp

__device__ __forceinline__ float4 ldcs_pf256(const float4* p)
{
    float4 v;
    asm volatile("ld.global.cs.L2::256B.v4.f32 {%0,%1,%2,%3}, [%4];"
                 : "=f"(v.x), "=f"(v.y), "=f"(v.z), "=f"(v.w)
                 : "l"(p));
    return v;
}

__device__ __forceinline__ void rodrigues9(float x, float y, float z, float* __restrict__ r)
{
    float n2    = fmaf(x, x, fmaf(y, y, z * z));
    float theta = fmaxf(sqrtf(n2), 1e-5f);
    float inv   = __fdividef(1.0f, theta);
    float a0 = x * inv, a1 = y * inv, a2 = z * inv;

    float s, c;
    __sincosf(theta, &s, &c);
    float k = 1.0f - c;

    // R = c*I + s*[a]_x + k*(a a^T)
    float ka0 = k * a0, ka1 = k * a1;
    float sa0 = s * a0, sa1 = s * a1, sa2 = s * a2;

    r[0] = fmaf(ka0, a0, c);
    r[1] = fmaf(ka0, a1, -sa2);
    r[2] = fmaf(ka0, a2,  sa1);
    r[3] = fmaf(ka0, a1,  sa2);
    r[4] = fmaf(ka1, a1, c);
    r[5] = fmaf(ka1, a2, -sa0);
    r[6] = fmaf(ka0, a2, -sa1);
    r[7] = fmaf(ka1, a2,  sa0);
    r[8] = fmaf(k * a2, a2, c);
}

__global__ __launch_bounds__(TPB)
void twist2mat_kernel(const float4* __restrict__ in4,
                      float4* __restrict__ out4,
                      int n_elems)
{
    __shared__ float s_in [WARPS][TILES * 96];                 // 1536 B / warp
    __shared__ __align__(16) float s_out[WARPS][2][576];       // 2 x 2304 B / warp

    const int lane = threadIdx.x & 31;
    const int wrp  = threadIdx.x >> 5;
    const long long wstart = ((long long)blockIdx.x * WARPS + wrp) * (32 * TILES);
    if (wstart >= n_elems) return;

    const float4* gin  = in4  + wstart / 4 * 3;   // wstart*3/4
    float4*       gout = out4 + wstart / 4 * 9;   // wstart*9/4

    const bool warp_full = (wstart + 32 * TILES <= n_elems);

    // ---- batched coalesced load: 96 float4 per warp (3 per lane),
    //      streaming + L2 256B prefetch hint ----
    if (warp_full) {
        float4* s = (float4*)s_in[wrp];
#pragma unroll
        for (int j = 0; j < 3; j++)
            s[lane + 32 * j] = ldcs_pf256(gin + lane + 32 * j);
    } else {
        const float* gf = (const float*)gin;
        int vf = (int)(n_elems - wstart) * 3;
        for (int i = lane; i < TILES * 96; i += 32)
            s_in[wrp][i] = (i < vf) ? gf[i] : 1.0f;   // pad, never stored
    }
    __syncwarp();

    if (warp_full) {
        // evict_first policy for the streaming write lines
        uint64_t pol;
        asm volatile("createpolicy.fractional.L2::evict_first.b64 %0, 1.0;" : "=l"(pol));

#pragma unroll
        for (int p = 0; p < TILES / 2; p++) {
            // ---- compute two tiles into one contiguous 2304B buffer ----
            float* sop = s_out[wrp][p];
#pragma unroll
            for (int sub = 0; sub < 2; sub++) {
                const int t = 2 * p + sub;
                const float* si = s_in[wrp] + t * 96;
                float x = si[3 * lane + 0];
                float y = si[3 * lane + 1];
                float z = si[3 * lane + 2];
                float r[9];
                rodrigues9(x, y, z, r);
                float* so = sop + sub * 288;
#pragma unroll
                for (int i = 0; i < 9; i++)
                    so[9 * lane + i] = r[i];          // stride-9 STS: conflict-free
            }
            __syncwarp();

            // ---- one TMA bulk store per pair: 2304 B, evict_first hint ----
            if (lane == 0) {
                asm volatile("fence.proxy.async.shared::cta;" ::: "memory");
                uint32_t src = (uint32_t)__cvta_generic_to_shared(sop);
                void* dst = (void*)(gout + p * 144);
                asm volatile(
                    "cp.async.bulk.global.shared::cta.bulk_group.L2::cache_hint "
                    "[%0], [%1], %2, %3;"
                    :: "l"(dst), "r"(src), "n"(2304), "l"(pol) : "memory");
                asm volatile("cp.async.bulk.commit_group;" ::: "memory");
            }
            // no mid-loop wait: each buffer is written exactly once
        }
        // Exit drain: smem-read completion only (safe for CTA retire);
        // do not wait for global write visibility.
        if (lane == 0)
            asm volatile("cp.async.bulk.wait_group.read 0;" ::: "memory");
    } else {
        // ---- scalar-safe tail path (not hit for this shape) ----
        for (int t = 0; t < TILES; t++) {
            const long long tbase = wstart + 32LL * t;
            if (tbase >= n_elems) break;
            const float* si = s_in[wrp] + t * 96;
            float r[9];
            rodrigues9(si[3 * lane], si[3 * lane + 1], si[3 * lane + 2], r);
            float* so = s_out[wrp][0];
#pragma unroll
            for (int i = 0; i < 9; i++)
                so[9 * lane + i] = r[i];
            __syncwarp();
            float* gf = (float*)(gout + t * 72);
            long long ve = n_elems - tbase;
            int vf = (int)((ve < 32 ? ve : 32) * 9);
            for (int i = lane; i < vf; i += 32)
                gf[i] = so[i];
            __syncwarp();
        }
    }
}

extern "C" void kernel_launch(void* const* d_in, const int* in_sizes, int n_in,
                              void* d_out, int out_size)
{
    const float* twist = (const float*)d_in[0];
    float* out = (float*)d_out;

    int n_elems = in_sizes[0] / 3;                       // 8,388,608
    long long per_block = (long long)WARPS * 32 * TILES; // 1024
    int blocks = (int)((n_elems + per_block - 1) / per_block);

    twist2mat_kernel<<<blocks, TPB>>>((const float4*)twist, (float4*)out, n_elems);
}